// round 11
// baseline (speedup 1.0000x reference)
#include <cuda_runtime.h>
#include <cuda_bf16.h>
#include <cuda_fp16.h>
#include <cstdint>
#include <math.h>

// M=4096, E=768. GEMM1 (x@Wp^T) bf16 3-term + fused quantum epilogue -> fp16 mid.
// GEMM2 (mid@Wc^T) single-product fp16 + bias.
// R10: mbarrier-pipelined mainloop, NO __syncthreads per chunk; warps decoupled
//      within the 3-stage window.
#define MM 4096
#define NNE 768
#define KK 768

// ---- GEMM1 ----
#define NCH1 24
#define ROWB 64
#define A_SM (128 * ROWB)
#define B_SM (64 * ROWB)
#define BUF_SM (2 * A_SM + 2 * B_SM)   // 24576
#define MB_OFF 73728                   // barriers after the 3 stages
#define SMEM1 73856
// ---- GEMM2 ----
#define NCH2 12
#define ROWB2 128
#define A_SM2 (128 * ROWB2)
#define B_SM2 (64 * ROWB2)
#define BUF2 (A_SM2 + B_SM2)           // 24576
#define SMEM2 73856
#define EPI_STRIDE 68

// ---------------- device globals ----------------
__device__ __align__(16) __nv_bfloat16 g_xh[(size_t)MM * KK], g_xl[(size_t)MM * KK];
__device__ __align__(16) __nv_bfloat16 g_wph[(size_t)KK * NNE], g_wpl[(size_t)KK * NNE];
__device__ __align__(16) __half g_wc[(size_t)KK * NNE];
__device__ __align__(16) __half g_mid[(size_t)MM * NNE];

// ---------------- helpers ----------------
__device__ __forceinline__ uint32_t pk2(__nv_bfloat16 a, __nv_bfloat16 b) {
    __nv_bfloat162 v = __halves2bfloat162(a, b);
    return *(uint32_t*)&v;
}
__device__ __forceinline__ uint32_t pkh2(__half a, __half b) {
    __half2 v = __halves2half2(a, b);
    return *(uint32_t*)&v;
}
__device__ __forceinline__ void ldsm4(uint32_t& r0, uint32_t& r1, uint32_t& r2, uint32_t& r3,
                                      uint32_t addr) {
    asm volatile("ldmatrix.sync.aligned.m8n8.x4.shared.b16 {%0,%1,%2,%3}, [%4];"
                 : "=r"(r0), "=r"(r1), "=r"(r2), "=r"(r3) : "r"(addr));
}
__device__ __forceinline__ void mma_bf16(float* d, const uint32_t* a, const uint32_t* b) {
    asm volatile("mma.sync.aligned.m16n8k16.row.col.f32.bf16.bf16.f32 "
                 "{%0,%1,%2,%3}, {%4,%5,%6,%7}, {%8,%9}, {%0,%1,%2,%3};"
                 : "+f"(d[0]), "+f"(d[1]), "+f"(d[2]), "+f"(d[3])
                 : "r"(a[0]), "r"(a[1]), "r"(a[2]), "r"(a[3]), "r"(b[0]), "r"(b[1]));
}
__device__ __forceinline__ void mma_f16(float* d, const uint32_t* a, const uint32_t* b) {
    asm volatile("mma.sync.aligned.m16n8k16.row.col.f32.f16.f16.f32 "
                 "{%0,%1,%2,%3}, {%4,%5,%6,%7}, {%8,%9}, {%0,%1,%2,%3};"
                 : "+f"(d[0]), "+f"(d[1]), "+f"(d[2]), "+f"(d[3])
                 : "r"(a[0]), "r"(a[1]), "r"(a[2]), "r"(a[3]), "r"(b[0]), "r"(b[1]));
}
__device__ __forceinline__ void cpa16(uint32_t dst, const void* src) {
    asm volatile("cp.async.cg.shared.global [%0], [%1], 16;" :: "r"(dst), "l"(src));
}
__device__ __forceinline__ void mbar_init(uint32_t a, uint32_t n) {
    asm volatile("mbarrier.init.shared.b64 [%0], %1;" :: "r"(a), "r"(n) : "memory");
}
__device__ __forceinline__ void mbar_arrive(uint32_t a) {
    asm volatile("mbarrier.arrive.shared.b64 _, [%0];" :: "r"(a) : "memory");
}
__device__ __forceinline__ void mbar_wait(uint32_t a, uint32_t ph) {
    asm volatile("{\n\t.reg .pred P;\n\tWL_%=:\n\t"
                 "mbarrier.try_wait.parity.acquire.cta.shared::cta.b64 P, [%0], %1, 0x989680;\n\t"
                 "@!P bra WL_%=;\n\t}" :: "r"(a), "r"(ph) : "memory");
}
__device__ __forceinline__ void cpa_mbar(uint32_t a) {
    asm volatile("cp.async.mbarrier.arrive.noinc.shared::cta.b64 [%0];" :: "r"(a) : "memory");
}

// ---------------- prep ----------------
template <int WHICH>  // 0: x, 1: W_proj
__global__ void split_kernel(const float* __restrict__ src, int n4) {
    int i = blockIdx.x * blockDim.x + threadIdx.x;
    if (i >= n4) return;
    __nv_bfloat16* hi = (WHICH == 0) ? g_xh : g_wph;
    __nv_bfloat16* lo = (WHICH == 0) ? g_xl : g_wpl;
    float4 v = ((const float4*)src)[i];
    float f[4] = {v.x, v.y, v.z, v.w};
    __nv_bfloat16 h[4], l[4];
#pragma unroll
    for (int j = 0; j < 4; j++) {
        h[j] = __float2bfloat16(f[j]);
        l[j] = __float2bfloat16(f[j] - __bfloat162float(h[j]));
    }
    *(uint2*)(hi + (size_t)i * 4) = make_uint2(pk2(h[0], h[1]), pk2(h[2], h[3]));
    *(uint2*)(lo + (size_t)i * 4) = make_uint2(pk2(l[0], l[1]), pk2(l[2], l[3]));
}

__global__ void conv_half_kernel(const float* __restrict__ src, int n4) {
    int i = blockIdx.x * blockDim.x + threadIdx.x;
    if (i >= n4) return;
    float4 v = ((const float4*)src)[i];
    *(uint2*)(g_wc + (size_t)i * 4) =
        make_uint2(pkh2(__float2half_rn(v.x), __float2half_rn(v.y)),
                   pkh2(__float2half_rn(v.z), __float2half_rn(v.w)));
}

// ---------------- GEMM1: bf16 3-term + quantum epilogue -> g_mid (fp16) ----
__global__ __launch_bounds__(256, 3)
void qgemm1_kernel(const float* __restrict__ bias, const float* __restrict__ theta)
{
    extern __shared__ __align__(16) char smem[];
    const uint32_t sb = (uint32_t)__cvta_generic_to_shared(smem);
    const uint32_t mb = sb + MB_OFF;
    const int t = threadIdx.x, lane = t & 31, wid = t >> 5;
    const int warp_m = wid >> 1, warp_n = wid & 1;   // warp tile 32x32
    const int bm = blockIdx.y * 128, bn = blockIdx.x * 64;

    const int ldRow = t >> 2, ldQ = t & 3;
    const __nv_bfloat16* srcA_h  = g_xh + (size_t)(bm + ldRow) * KK + ldQ * 8;
    const __nv_bfloat16* srcA_h2 = g_xh + (size_t)(bm + ldRow + 64) * KK + ldQ * 8;
    const __nv_bfloat16* srcA_l  = g_xl + (size_t)(bm + ldRow) * KK + ldQ * 8;
    const __nv_bfloat16* srcA_l2 = g_xl + (size_t)(bm + ldRow + 64) * KK + ldQ * 8;
    const __nv_bfloat16* srcB_h  = g_wph + (size_t)(bn + ldRow) * KK + ldQ * 8;
    const __nv_bfloat16* srcB_l  = g_wpl + (size_t)(bn + ldRow) * KK + ldQ * 8;
    const uint32_t dBase = sb + ldRow * ROWB + 16u * (ldQ ^ ((ldRow >> 1) & 3));

    const int aRow = warp_m * 32 + (lane & 15);
    const int aC   = lane >> 4;
    const int aSw  = (aRow >> 1) & 3;
    const uint32_t aBase = (uint32_t)(aRow * ROWB);
    const uint32_t aK0 = 16u * ((0 + aC) ^ aSw);
    const uint32_t aK1 = 16u * ((2 + aC) ^ aSw);
    const int bR  = warp_n * 32 + (lane & 7) + ((lane >> 4) & 1) * 8;
    const int bC  = (lane >> 3) & 1;
    const int bSw = (bR >> 1) & 3;
    const uint32_t bBase = (uint32_t)(2 * A_SM + bR * ROWB);
    const uint32_t bK0 = 16u * ((0 + bC) ^ bSw);
    const uint32_t bK1 = 16u * ((2 + bC) ^ bSw);

    if (t == 0) {
#pragma unroll
        for (int s = 0; s < 3; s++) {
            mbar_init(mb + s * 8, 256);       // full: 256 noinc cp.async arrivals
            mbar_init(mb + 24 + s * 8, 8);    // empty: 8 per-warp arrivals
        }
    }
    __syncthreads();

    float acc[2][4][4];
#pragma unroll
    for (int mt = 0; mt < 2; mt++)
#pragma unroll
        for (int nt = 0; nt < 4; nt++)
#pragma unroll
            for (int r = 0; r < 4; r++) acc[mt][nt][r] = 0.f;

    auto issue = [&](int c, int s) {
        const int ko = c * 32;
        const uint32_t d0 = dBase + s * BUF_SM;
        cpa16(d0,                        srcA_h + ko);
        cpa16(d0 + 64 * ROWB,            srcA_h2 + ko);
        cpa16(d0 + A_SM,                 srcA_l + ko);
        cpa16(d0 + A_SM + 64 * ROWB,     srcA_l2 + ko);
        cpa16(d0 + 2 * A_SM,             srcB_h + ko);
        cpa16(d0 + 2 * A_SM + B_SM,      srcB_l + ko);
    };

    // prologue: fill all 3 stages
    issue(0, 0); cpa_mbar(mb + 0);
    issue(1, 1); cpa_mbar(mb + 8);
    issue(2, 2); cpa_mbar(mb + 16);

    int s = 0, ph = 0;
    for (int c = 0; c < NCH1; ++c) {
        const uint32_t fullb = mb + s * 8, emptyb = mb + 24 + s * 8;
        mbar_wait(fullb, ph);

        const uint32_t bufB = sb + s * BUF_SM;
#pragma unroll
        for (int ks = 0; ks < 2; ks++) {
            const uint32_t aKo = ks ? aK1 : aK0;
            const uint32_t bKo = ks ? bK1 : bK0;
            uint32_t bh[4][2], bl[4][2], af[2][4];
#pragma unroll
            for (int np = 0; np < 2; np++) {
                ldsm4(bh[2 * np][0], bh[2 * np][1], bh[2 * np + 1][0], bh[2 * np + 1][1],
                      bufB + bBase + np * (16 * ROWB) + bKo);
                ldsm4(bl[2 * np][0], bl[2 * np][1], bl[2 * np + 1][0], bl[2 * np + 1][1],
                      bufB + bBase + B_SM + np * (16 * ROWB) + bKo);
            }
#pragma unroll
            for (int mt = 0; mt < 2; mt++)
                ldsm4(af[mt][0], af[mt][1], af[mt][2], af[mt][3],
                      bufB + aBase + mt * (16 * ROWB) + aKo);
#pragma unroll
            for (int mt = 0; mt < 2; mt++)
#pragma unroll
                for (int nt = 0; nt < 4; nt++) mma_bf16(acc[mt][nt], af[mt], bh[nt]);
#pragma unroll
            for (int mt = 0; mt < 2; mt++)
#pragma unroll
                for (int nt = 0; nt < 4; nt++) mma_bf16(acc[mt][nt], af[mt], bl[nt]);
#pragma unroll
            for (int mt = 0; mt < 2; mt++)
                ldsm4(af[mt][0], af[mt][1], af[mt][2], af[mt][3],
                      bufB + A_SM + aBase + mt * (16 * ROWB) + aKo);
#pragma unroll
            for (int mt = 0; mt < 2; mt++)
#pragma unroll
                for (int nt = 0; nt < 4; nt++) mma_bf16(acc[mt][nt], af[mt], bh[nt]);
        }

        __syncwarp();
        if (lane == 0) mbar_arrive(emptyb);
        if (c + 3 < NCH1) {
            mbar_wait(emptyb, ph);    // all warps done with chunk c on stage s
            issue(c + 3, s);
            cpa_mbar(fullb);
        }
        if (++s == 3) { s = 0; ph ^= 1; }
    }
    __syncthreads();   // all warps finished all chunks; smem reusable

    // stage accumulators for head-aligned epilogue
    float* smf = (float*)smem;
#pragma unroll
    for (int mt = 0; mt < 2; mt++)
#pragma unroll
        for (int nt = 0; nt < 4; nt++) {
            int r0 = warp_m * 32 + mt * 16 + (lane >> 2);
            int col = warp_n * 32 + nt * 8 + (lane & 3) * 2;
            smf[r0 * EPI_STRIDE + col]           = acc[mt][nt][0];
            smf[r0 * EPI_STRIDE + col + 1]       = acc[mt][nt][1];
            smf[(r0 + 8) * EPI_STRIDE + col]     = acc[mt][nt][2];
            smf[(r0 + 8) * EPI_STRIDE + col + 1] = acc[mt][nt][3];
        }
    __syncthreads();

    float th[8];
#pragma unroll
    for (int j = 0; j < 8; j++) th[j] = theta[j];
#pragma unroll
    for (int i = 0; i < 4; i++) {
        int gid = t + i * 256;
        int row = gid >> 3, head = gid & 7;
        const float* src = smf + row * EPI_STRIDE + head * 8;
        float cc[8];
#pragma unroll
        for (int j = 0; j < 8; j++)
            cc[j] = cosf(src[j] + bias[bn + head * 8 + j] + th[j]);
        float o[8];
        float p = cc[0];
#pragma unroll
        for (int w = 1; w < 8; w++) { p *= cc[w]; o[w] = p; }
        float q = cc[1];
#pragma unroll
        for (int w = 2; w < 8; w++) q *= cc[w];
        o[0] = q;
        __half h[8];
#pragma unroll
        for (int j = 0; j < 8; j++) h[j] = __float2half_rn(o[j]);
        size_t doff = (size_t)(bm + row) * NNE + bn + head * 8;
        *(uint4*)(g_mid + doff) = make_uint4(pkh2(h[0], h[1]), pkh2(h[2], h[3]),
                                             pkh2(h[4], h[5]), pkh2(h[6], h[7]));
    }
}

// ---------------- GEMM2: fp16 single product + bias -> out ----------------
__global__ __launch_bounds__(256, 3)
void qgemm2_kernel(const float* __restrict__ bias, float* __restrict__ out)
{
    extern __shared__ __align__(16) char smem[];
    const uint32_t sb = (uint32_t)__cvta_generic_to_shared(smem);
    const uint32_t mb = sb + MB_OFF;
    const int t = threadIdx.x, lane = t & 31, wid = t >> 5;
    const int warp_m = wid >> 1, warp_n = wid & 1;
    const int bm = blockIdx.y * 128, bn = blockIdx.x * 64;

    const int ldRow = t >> 3, ldSeg = t & 7;
    const __half* srcA0 = g_mid + (size_t)(bm + ldRow) * KK + ldSeg * 8;
    const __half* srcA1 = g_mid + (size_t)(bm + ldRow + 32) * KK + ldSeg * 8;
    const __half* srcA2 = g_mid + (size_t)(bm + ldRow + 64) * KK + ldSeg * 8;
    const __half* srcA3 = g_mid + (size_t)(bm + ldRow + 96) * KK + ldSeg * 8;
    const __half* srcB0 = g_wc + (size_t)(bn + ldRow) * KK + ldSeg * 8;
    const __half* srcB1 = g_wc + (size_t)(bn + ldRow + 32) * KK + ldSeg * 8;
    const uint32_t dBase = sb + ldRow * ROWB2 + 16u * (ldSeg ^ (ldRow & 7));

    const int aRow = warp_m * 32 + (lane & 15);
    const int aC   = lane >> 4;
    const int aXor = aRow & 7;
    const uint32_t aBase = (uint32_t)(aRow * ROWB2);
    uint32_t aK[4];
#pragma unroll
    for (int ks = 0; ks < 4; ks++) aK[ks] = 16u * ((2 * ks + aC) ^ aXor);
    const int bR  = warp_n * 32 + (lane & 7) + ((lane >> 4) & 1) * 8;
    const int bC  = (lane >> 3) & 1;
    const int bXor = bR & 7;
    const uint32_t bBase = (uint32_t)(A_SM2 + bR * ROWB2);
    uint32_t bK[4];
#pragma unroll
    for (int ks = 0; ks < 4; ks++) bK[ks] = 16u * ((2 * ks + bC) ^ bXor);

    if (t == 0) {
#pragma unroll
        for (int s = 0; s < 3; s++) {
            mbar_init(mb + s * 8, 256);
            mbar_init(mb + 24 + s * 8, 8);
        }
    }
    __syncthreads();

    float acc[2][4][4];
#pragma unroll
    for (int mt = 0; mt < 2; mt++)
#pragma unroll
        for (int nt = 0; nt < 4; nt++)
#pragma unroll
            for (int r = 0; r < 4; r++) acc[mt][nt][r] = 0.f;

    auto issue = [&](int c, int s) {
        const int ko = c * 64;
        const uint32_t d0 = dBase + s * BUF2;
        cpa16(d0,                      srcA0 + ko);
        cpa16(d0 + 32 * ROWB2,         srcA1 + ko);
        cpa16(d0 + 64 * ROWB2,         srcA2 + ko);
        cpa16(d0 + 96 * ROWB2,         srcA3 + ko);
        cpa16(d0 + A_SM2,              srcB0 + ko);
        cpa16(d0 + A_SM2 + 32 * ROWB2, srcB1 + ko);
    };

    issue(0, 0); cpa_mbar(mb + 0);
    issue(1, 1); cpa_mbar(mb + 8);
    issue(2, 2); cpa_mbar(mb + 16);

    int s = 0, ph = 0;
    for (int c = 0; c < NCH2; ++c) {
        const uint32_t fullb = mb + s * 8, emptyb = mb + 24 + s * 8;
        mbar_wait(fullb, ph);

        const uint32_t bufB = sb + s * BUF2;
#pragma unroll
        for (int ks = 0; ks < 4; ks++) {
            uint32_t bh[4][2], af[2][4];
#pragma unroll
            for (int np = 0; np < 2; np++)
                ldsm4(bh[2 * np][0], bh[2 * np][1], bh[2 * np + 1][0], bh[2 * np + 1][1],
                      bufB + bBase + np * (16 * ROWB2) + bK[ks]);
#pragma unroll
            for (int mt = 0; mt < 2; mt++)
                ldsm4(af[mt][0], af[mt][1], af[mt][2], af[mt][3],
                      bufB + aBase + mt * (16 * ROWB2) + aK[ks]);
#pragma unroll
            for (int mt = 0; mt < 2; mt++)
#pragma unroll
                for (int nt = 0; nt < 4; nt++) mma_f16(acc[mt][nt], af[mt], bh[nt]);
        }

        __syncwarp();
        if (lane == 0) mbar_arrive(emptyb);
        if (c + 3 < NCH2) {
            mbar_wait(emptyb, ph);
            issue(c + 3, s);
            cpa_mbar(fullb);
        }
        if (++s == 3) { s = 0; ph ^= 1; }
    }
    __syncthreads();

    float* smf = (float*)smem;
#pragma unroll
    for (int mt = 0; mt < 2; mt++)
#pragma unroll
        for (int nt = 0; nt < 4; nt++) {
            int r0 = warp_m * 32 + mt * 16 + (lane >> 2);
            int col = warp_n * 32 + nt * 8 + (lane & 3) * 2;
            smf[r0 * EPI_STRIDE + col]           = acc[mt][nt][0];
            smf[r0 * EPI_STRIDE + col + 1]       = acc[mt][nt][1];
            smf[(r0 + 8) * EPI_STRIDE + col]     = acc[mt][nt][2];
            smf[(r0 + 8) * EPI_STRIDE + col + 1] = acc[mt][nt][3];
        }
    __syncthreads();

#pragma unroll
    for (int i = 0; i < 8; i++) {
        int idx = t + i * 256;
        int row = idx >> 4, c4 = idx & 15;
        const float* src = smf + row * EPI_STRIDE + c4 * 4;
        float4 v;
        v.x = src[0] + bias[bn + c4 * 4 + 0];
        v.y = src[1] + bias[bn + c4 * 4 + 1];
        v.z = src[2] + bias[bn + c4 * 4 + 2];
        v.w = src[3] + bias[bn + c4 * 4 + 3];
        *(float4*)(out + (size_t)(bm + row) * NNE + bn + c4 * 4) = v;
    }
}

// ---------------- launch ----------------
extern "C" void kernel_launch(void* const* d_in, const int* in_sizes, int n_in,
                              void* d_out, int out_size)
{
    const float* x      = (const float*)d_in[0];
    const float* W_proj = (const float*)d_in[1];
    const float* b_proj = (const float*)d_in[2];
    const float* theta  = (const float*)d_in[3];
    const float* W_comb = (const float*)d_in[4];
    const float* b_comb = (const float*)d_in[5];
    float* out = (float*)d_out;

    cudaFuncSetAttribute(qgemm1_kernel, cudaFuncAttributeMaxDynamicSharedMemorySize, SMEM1);
    cudaFuncSetAttribute(qgemm2_kernel, cudaFuncAttributeMaxDynamicSharedMemorySize, SMEM2);

    int n4 = MM * KK / 4;
    split_kernel<0><<<(n4 + 255) / 256, 256>>>(x, n4);
    int w4 = KK * NNE / 4;
    split_kernel<1><<<(w4 + 255) / 256, 256>>>(W_proj, w4);
    conv_half_kernel<<<(w4 + 255) / 256, 256>>>(W_comb, w4);

    dim3 grid(NNE / 64, MM / 128);  // (12, 32) = 384 CTAs
    qgemm1_kernel<<<grid, 256, SMEM1>>>(b_proj, theta);
    qgemm2_kernel<<<grid, 256, SMEM2>>>(b_comb, out);
}

// round 14
// speedup vs baseline: 1.1748x; 1.1748x over previous
#include <cuda_runtime.h>
#include <cuda_bf16.h>
#include <cuda_fp16.h>
#include <cstdint>
#include <math.h>

// M=4096, E=768. GEMM1 (x@Wp^T) bf16 3-term + fused quantum epilogue -> fp16 mid.
// GEMM2 (mid@Wc^T) single-product fp16 + bias (R9-proven wait_group pipeline).
// R12: qgemm1 uses a ROTATING SINGLE-WARP ISSUER per chunk -> non-issuing warps
//      have true 3-stage skew freedom (no per-chunk all-warp rendezvous).
#define MM 4096
#define NNE 768
#define KK 768

// ---- GEMM1 ----
#define NCH1 24
#define ROWB 64
#define A_SM (128 * ROWB)
#define B_SM (64 * ROWB)
#define BUF_SM (2 * A_SM + 2 * B_SM)   // 24576
#define MB_OFF 73728
#define SMEM1 73856
// ---- GEMM2 ----
#define NCH2 12
#define ROWB2 128
#define A_SM2 (128 * ROWB2)
#define B_SM2 (64 * ROWB2)
#define BUF2 (A_SM2 + B_SM2)           // 24576
#define SMEM2 (3 * BUF2)               // 73728
#define EPI_STRIDE 68

// ---------------- device globals ----------------
__device__ __align__(16) __nv_bfloat16 g_xh[(size_t)MM * KK], g_xl[(size_t)MM * KK];
__device__ __align__(16) __nv_bfloat16 g_wph[(size_t)KK * NNE], g_wpl[(size_t)KK * NNE];
__device__ __align__(16) __half g_wc[(size_t)KK * NNE];
__device__ __align__(16) __half g_mid[(size_t)MM * NNE];

// ---------------- helpers ----------------
__device__ __forceinline__ uint32_t pk2(__nv_bfloat16 a, __nv_bfloat16 b) {
    __nv_bfloat162 v = __halves2bfloat162(a, b);
    return *(uint32_t*)&v;
}
__device__ __forceinline__ uint32_t pkh2(__half a, __half b) {
    __half2 v = __halves2half2(a, b);
    return *(uint32_t*)&v;
}
__device__ __forceinline__ void ldsm4(uint32_t& r0, uint32_t& r1, uint32_t& r2, uint32_t& r3,
                                      uint32_t addr) {
    asm volatile("ldmatrix.sync.aligned.m8n8.x4.shared.b16 {%0,%1,%2,%3}, [%4];"
                 : "=r"(r0), "=r"(r1), "=r"(r2), "=r"(r3) : "r"(addr));
}
__device__ __forceinline__ void mma_bf16(float* d, const uint32_t* a, const uint32_t* b) {
    asm volatile("mma.sync.aligned.m16n8k16.row.col.f32.bf16.bf16.f32 "
                 "{%0,%1,%2,%3}, {%4,%5,%6,%7}, {%8,%9}, {%0,%1,%2,%3};"
                 : "+f"(d[0]), "+f"(d[1]), "+f"(d[2]), "+f"(d[3])
                 : "r"(a[0]), "r"(a[1]), "r"(a[2]), "r"(a[3]), "r"(b[0]), "r"(b[1]));
}
__device__ __forceinline__ void mma_f16(float* d, const uint32_t* a, const uint32_t* b) {
    asm volatile("mma.sync.aligned.m16n8k16.row.col.f32.f16.f16.f32 "
                 "{%0,%1,%2,%3}, {%4,%5,%6,%7}, {%8,%9}, {%0,%1,%2,%3};"
                 : "+f"(d[0]), "+f"(d[1]), "+f"(d[2]), "+f"(d[3])
                 : "r"(a[0]), "r"(a[1]), "r"(a[2]), "r"(a[3]), "r"(b[0]), "r"(b[1]));
}
__device__ __forceinline__ void cpa16(uint32_t dst, const void* src) {
    asm volatile("cp.async.cg.shared.global [%0], [%1], 16;" :: "r"(dst), "l"(src));
}
__device__ __forceinline__ void mbar_init(uint32_t a, uint32_t n) {
    asm volatile("mbarrier.init.shared.b64 [%0], %1;" :: "r"(a), "r"(n) : "memory");
}
__device__ __forceinline__ void mbar_arrive(uint32_t a) {
    asm volatile("mbarrier.arrive.shared.b64 _, [%0];" :: "r"(a) : "memory");
}
__device__ __forceinline__ void mbar_wait(uint32_t a, uint32_t ph) {
    asm volatile("{\n\t.reg .pred P;\n\tWL_%=:\n\t"
                 "mbarrier.try_wait.parity.acquire.cta.shared::cta.b64 P, [%0], %1, 0x989680;\n\t"
                 "@!P bra WL_%=;\n\t}" :: "r"(a), "r"(ph) : "memory");
}
__device__ __forceinline__ void cpa_mbar(uint32_t a) {
    asm volatile("cp.async.mbarrier.arrive.noinc.shared::cta.b64 [%0];" :: "r"(a) : "memory");
}

// ---------------- prep ----------------
template <int WHICH>  // 0: x, 1: W_proj
__global__ void split_kernel(const float* __restrict__ src, int n4) {
    int i = blockIdx.x * blockDim.x + threadIdx.x;
    if (i >= n4) return;
    __nv_bfloat16* hi = (WHICH == 0) ? g_xh : g_wph;
    __nv_bfloat16* lo = (WHICH == 0) ? g_xl : g_wpl;
    float4 v = ((const float4*)src)[i];
    float f[4] = {v.x, v.y, v.z, v.w};
    __nv_bfloat16 h[4], l[4];
#pragma unroll
    for (int j = 0; j < 4; j++) {
        h[j] = __float2bfloat16(f[j]);
        l[j] = __float2bfloat16(f[j] - __bfloat162float(h[j]));
    }
    *(uint2*)(hi + (size_t)i * 4) = make_uint2(pk2(h[0], h[1]), pk2(h[2], h[3]));
    *(uint2*)(lo + (size_t)i * 4) = make_uint2(pk2(l[0], l[1]), pk2(l[2], l[3]));
}

__global__ void conv_half_kernel(const float* __restrict__ src, int n4) {
    int i = blockIdx.x * blockDim.x + threadIdx.x;
    if (i >= n4) return;
    float4 v = ((const float4*)src)[i];
    *(uint2*)(g_wc + (size_t)i * 4) =
        make_uint2(pkh2(__float2half_rn(v.x), __float2half_rn(v.y)),
                   pkh2(__float2half_rn(v.z), __float2half_rn(v.w)));
}

// ---------------- GEMM1: bf16 3-term, rotating-issuer mbarrier pipeline ----
__global__ __launch_bounds__(256, 3)
void qgemm1_kernel(const float* __restrict__ bias, const float* __restrict__ theta)
{
    extern __shared__ __align__(16) char smem[];
    const uint32_t sb = (uint32_t)__cvta_generic_to_shared(smem);
    const uint32_t mb = sb + MB_OFF;
    const int t = threadIdx.x, lane = t & 31, wid = t >> 5;
    const int warp_m = wid >> 1, warp_n = wid & 1;   // warp tile 32x32
    const int bm = blockIdx.y * 128, bn = blockIdx.x * 64;

    const int aRow = warp_m * 32 + (lane & 15);
    const int aC   = lane >> 4;
    const int aSw  = (aRow >> 1) & 3;
    const uint32_t aBase = (uint32_t)(aRow * ROWB);
    const uint32_t aK0 = 16u * ((0 + aC) ^ aSw);
    const uint32_t aK1 = 16u * ((2 + aC) ^ aSw);
    const int bR  = warp_n * 32 + (lane & 7) + ((lane >> 4) & 1) * 8;
    const int bC  = (lane >> 3) & 1;
    const int bSw = (bR >> 1) & 3;
    const uint32_t bBase = (uint32_t)(2 * A_SM + bR * ROWB);
    const uint32_t bK0 = 16u * ((0 + bC) ^ bSw);
    const uint32_t bK1 = 16u * ((2 + bC) ^ bSw);

    if (t == 0) {
#pragma unroll
        for (int s = 0; s < 3; s++) {
            mbar_init(mb + s * 8, 32);        // full: 32 noinc arrivals (one warp)
            mbar_init(mb + 24 + s * 8, 8);    // empty: 8 per-warp arrivals
        }
    }
    __syncthreads();

    // single-warp chunk issue: 32 lanes x 8 iters x 6 cp.async = whole chunk
    auto issue_chunk = [&](int c, int s) {
        const int ko = c * 32;
        const uint32_t d0 = sb + s * BUF_SM;
#pragma unroll
        for (int i = 0; i < 8; i++) {
            int tt = lane + 32 * i;
            int row = tt >> 2, q = tt & 3;
            uint32_t dst = d0 + row * ROWB + 16u * (q ^ ((row >> 1) & 3));
            size_t goff = (size_t)(bm + row) * KK + ko + q * 8;
            size_t goff2 = goff + (size_t)64 * KK;
            size_t boff = (size_t)(bn + row) * KK + ko + q * 8;
            cpa16(dst,                    g_xh + goff);
            cpa16(dst + 64 * ROWB,        g_xh + goff2);
            cpa16(dst + A_SM,             g_xl + goff);
            cpa16(dst + A_SM + 64 * ROWB, g_xl + goff2);
            cpa16(dst + 2 * A_SM,         g_wph + boff);
            cpa16(dst + 2 * A_SM + B_SM,  g_wpl + boff);
        }
        cpa_mbar(mb + s * 8);
    };

    // prologue: warps 5,6,7 issue chunks 0,1,2 (chunk k issued by warp (k+5)&7)
    if (wid >= 5) issue_chunk(wid - 5, wid - 5);

    float acc[2][4][4];
#pragma unroll
    for (int mt = 0; mt < 2; mt++)
#pragma unroll
        for (int nt = 0; nt < 4; nt++)
#pragma unroll
            for (int r = 0; r < 4; r++) acc[mt][nt][r] = 0.f;

    int s = 0, ph = 0;
    for (int c = 0; c < NCH1; ++c) {
        const uint32_t fullb = mb + s * 8, emptyb = mb + 24 + s * 8;
        mbar_wait(fullb, ph);

        const uint32_t bufB = sb + s * BUF_SM;
#pragma unroll
        for (int ks = 0; ks < 2; ks++) {
            const uint32_t aKo = ks ? aK1 : aK0;
            const uint32_t bKo = ks ? bK1 : bK0;
            uint32_t bh[4][2], bl[4][2], af[2][4];
#pragma unroll
            for (int np = 0; np < 2; np++) {
                ldsm4(bh[2 * np][0], bh[2 * np][1], bh[2 * np + 1][0], bh[2 * np + 1][1],
                      bufB + bBase + np * (16 * ROWB) + bKo);
                ldsm4(bl[2 * np][0], bl[2 * np][1], bl[2 * np + 1][0], bl[2 * np + 1][1],
                      bufB + bBase + B_SM + np * (16 * ROWB) + bKo);
            }
#pragma unroll
            for (int mt = 0; mt < 2; mt++)
                ldsm4(af[mt][0], af[mt][1], af[mt][2], af[mt][3],
                      bufB + aBase + mt * (16 * ROWB) + aKo);
#pragma unroll
            for (int mt = 0; mt < 2; mt++)
#pragma unroll
                for (int nt = 0; nt < 4; nt++) mma_bf16(acc[mt][nt], af[mt], bh[nt]);
#pragma unroll
            for (int mt = 0; mt < 2; mt++)
#pragma unroll
                for (int nt = 0; nt < 4; nt++) mma_bf16(acc[mt][nt], af[mt], bl[nt]);
#pragma unroll
            for (int mt = 0; mt < 2; mt++)
                ldsm4(af[mt][0], af[mt][1], af[mt][2], af[mt][3],
                      bufB + A_SM + aBase + mt * (16 * ROWB) + aKo);
#pragma unroll
            for (int mt = 0; mt < 2; mt++)
#pragma unroll
                for (int nt = 0; nt < 4; nt++) mma_bf16(acc[mt][nt], af[mt], bh[nt]);
        }

        __syncwarp();
        if (lane == 0) mbar_arrive(emptyb);
        // ONLY warp (c&7) pays the empty-wait and issues chunk c+3; other
        // warps advance immediately (true 3-stage skew window).
        if (wid == (c & 7) && c + 3 < NCH1) {
            mbar_wait(emptyb, ph);
            issue_chunk(c + 3, s);
        }
        if (++s == 3) { s = 0; ph ^= 1; }
    }
    __syncthreads();

    float* smf = (float*)smem;
#pragma unroll
    for (int mt = 0; mt < 2; mt++)
#pragma unroll
        for (int nt = 0; nt < 4; nt++) {
            int r0 = warp_m * 32 + mt * 16 + (lane >> 2);
            int col = warp_n * 32 + nt * 8 + (lane & 3) * 2;
            smf[r0 * EPI_STRIDE + col]           = acc[mt][nt][0];
            smf[r0 * EPI_STRIDE + col + 1]       = acc[mt][nt][1];
            smf[(r0 + 8) * EPI_STRIDE + col]     = acc[mt][nt][2];
            smf[(r0 + 8) * EPI_STRIDE + col + 1] = acc[mt][nt][3];
        }
    __syncthreads();

    float th[8];
#pragma unroll
    for (int j = 0; j < 8; j++) th[j] = theta[j];
#pragma unroll
    for (int i = 0; i < 4; i++) {
        int gid = t + i * 256;
        int row = gid >> 3, head = gid & 7;
        const float* src = smf + row * EPI_STRIDE + head * 8;
        float cc[8];
#pragma unroll
        for (int j = 0; j < 8; j++)
            cc[j] = cosf(src[j] + bias[bn + head * 8 + j] + th[j]);
        float o[8];
        float p = cc[0];
#pragma unroll
        for (int w = 1; w < 8; w++) { p *= cc[w]; o[w] = p; }
        float q = cc[1];
#pragma unroll
        for (int w = 2; w < 8; w++) q *= cc[w];
        o[0] = q;
        __half h[8];
#pragma unroll
        for (int j = 0; j < 8; j++) h[j] = __float2half_rn(o[j]);
        size_t doff = (size_t)(bm + row) * NNE + bn + head * 8;
        *(uint4*)(g_mid + doff) = make_uint4(pkh2(h[0], h[1]), pkh2(h[2], h[3]),
                                             pkh2(h[4], h[5]), pkh2(h[6], h[7]));
    }
}

// ---------------- GEMM2: fp16 single product + bias (R9-proven) ----------------
__global__ __launch_bounds__(256, 3)
void qgemm2_kernel(const float* __restrict__ bias, float* __restrict__ out)
{
    extern __shared__ __align__(16) char smem[];
    const uint32_t sb = (uint32_t)__cvta_generic_to_shared(smem);
    const int t = threadIdx.x, lane = t & 31, wid = t >> 5;
    const int warp_m = wid >> 1, warp_n = wid & 1;
    const int bm = blockIdx.y * 128, bn = blockIdx.x * 64;

    const int ldRow = t >> 3, ldSeg = t & 7;
    const __half* srcA0 = g_mid + (size_t)(bm + ldRow) * KK + ldSeg * 8;
    const __half* srcA1 = g_mid + (size_t)(bm + ldRow + 32) * KK + ldSeg * 8;
    const __half* srcA2 = g_mid + (size_t)(bm + ldRow + 64) * KK + ldSeg * 8;
    const __half* srcA3 = g_mid + (size_t)(bm + ldRow + 96) * KK + ldSeg * 8;
    const __half* srcB0 = g_wc + (size_t)(bn + ldRow) * KK + ldSeg * 8;
    const __half* srcB1 = g_wc + (size_t)(bn + ldRow + 32) * KK + ldSeg * 8;
    const uint32_t dBase = sb + ldRow * ROWB2 + 16u * (ldSeg ^ (ldRow & 7));

    const int aRow = warp_m * 32 + (lane & 15);
    const int aC   = lane >> 4;
    const int aXor = aRow & 7;
    const uint32_t aBase = (uint32_t)(aRow * ROWB2);
    uint32_t aK[4];
#pragma unroll
    for (int ks = 0; ks < 4; ks++) aK[ks] = 16u * ((2 * ks + aC) ^ aXor);
    const int bR  = warp_n * 32 + (lane & 7) + ((lane >> 4) & 1) * 8;
    const int bC  = (lane >> 3) & 1;
    const int bXor = bR & 7;
    const uint32_t bBase = (uint32_t)(A_SM2 + bR * ROWB2);
    uint32_t bK[4];
#pragma unroll
    for (int ks = 0; ks < 4; ks++) bK[ks] = 16u * ((2 * ks + bC) ^ bXor);

    float acc[2][4][4];
#pragma unroll
    for (int mt = 0; mt < 2; mt++)
#pragma unroll
        for (int nt = 0; nt < 4; nt++)
#pragma unroll
            for (int r = 0; r < 4; r++) acc[mt][nt][r] = 0.f;

    auto issue = [&](int c, int b) {
        const int ko = c * 64;
        const uint32_t d0 = dBase + b * BUF2;
        cpa16(d0,                      srcA0 + ko);
        cpa16(d0 + 32 * ROWB2,         srcA1 + ko);
        cpa16(d0 + 64 * ROWB2,         srcA2 + ko);
        cpa16(d0 + 96 * ROWB2,         srcA3 + ko);
        cpa16(d0 + A_SM2,              srcB0 + ko);
        cpa16(d0 + A_SM2 + 32 * ROWB2, srcB1 + ko);
        asm volatile("cp.async.commit_group;" ::: "memory");
    };

    issue(0, 0);
    issue(1, 1);
    int buf = 0;
    for (int c = 0; c < NCH2; ++c) {
        asm volatile("cp.async.wait_group 1;" ::: "memory");
        __syncthreads();
        if (c + 2 < NCH2) issue(c + 2, (buf + 2 >= 3) ? buf - 1 : buf + 2);

        const uint32_t bufB = sb + buf * BUF2;
#pragma unroll
        for (int ks = 0; ks < 4; ks++) {
            uint32_t bh[4][2], af[2][4];
#pragma unroll
            for (int np = 0; np < 2; np++)
                ldsm4(bh[2 * np][0], bh[2 * np][1], bh[2 * np + 1][0], bh[2 * np + 1][1],
                      bufB + bBase + np * (16 * ROWB2) + bK[ks]);
#pragma unroll
            for (int mt = 0; mt < 2; mt++)
                ldsm4(af[mt][0], af[mt][1], af[mt][2], af[mt][3],
                      bufB + aBase + mt * (16 * ROWB2) + aK[ks]);
#pragma unroll
            for (int mt = 0; mt < 2; mt++)
#pragma unroll
                for (int nt = 0; nt < 4; nt++) mma_f16(acc[mt][nt], af[mt], bh[nt]);
        }
        buf = (buf + 1 >= 3) ? 0 : buf + 1;
    }

    float* smf = (float*)smem;
#pragma unroll
    for (int mt = 0; mt < 2; mt++)
#pragma unroll
        for (int nt = 0; nt < 4; nt++) {
            int r0 = warp_m * 32 + mt * 16 + (lane >> 2);
            int col = warp_n * 32 + nt * 8 + (lane & 3) * 2;
            smf[r0 * EPI_STRIDE + col]           = acc[mt][nt][0];
            smf[r0 * EPI_STRIDE + col + 1]       = acc[mt][nt][1];
            smf[(r0 + 8) * EPI_STRIDE + col]     = acc[mt][nt][2];
            smf[(r0 + 8) * EPI_STRIDE + col + 1] = acc[mt][nt][3];
        }
    __syncthreads();

#pragma unroll
    for (int i = 0; i < 8; i++) {
        int idx = t + i * 256;
        int row = idx >> 4, c4 = idx & 15;
        const float* src = smf + row * EPI_STRIDE + c4 * 4;
        float4 v;
        v.x = src[0] + bias[bn + c4 * 4 + 0];
        v.y = src[1] + bias[bn + c4 * 4 + 1];
        v.z = src[2] + bias[bn + c4 * 4 + 2];
        v.w = src[3] + bias[bn + c4 * 4 + 3];
        *(float4*)(out + (size_t)(bm + row) * NNE + bn + c4 * 4) = v;
    }
}

// ---------------- launch ----------------
extern "C" void kernel_launch(void* const* d_in, const int* in_sizes, int n_in,
                              void* d_out, int out_size)
{
    const float* x      = (const float*)d_in[0];
    const float* W_proj = (const float*)d_in[1];
    const float* b_proj = (const float*)d_in[2];
    const float* theta  = (const float*)d_in[3];
    const float* W_comb = (const float*)d_in[4];
    const float* b_comb = (const float*)d_in[5];
    float* out = (float*)d_out;

    cudaFuncSetAttribute(qgemm1_kernel, cudaFuncAttributeMaxDynamicSharedMemorySize, SMEM1);
    cudaFuncSetAttribute(qgemm2_kernel, cudaFuncAttributeMaxDynamicSharedMemorySize, SMEM2);

    int n4 = MM * KK / 4;
    split_kernel<0><<<(n4 + 255) / 256, 256>>>(x, n4);
    int w4 = KK * NNE / 4;
    split_kernel<1><<<(w4 + 255) / 256, 256>>>(W_proj, w4);
    conv_half_kernel<<<(w4 + 255) / 256, 256>>>(W_comb, w4);

    dim3 grid(NNE / 64, MM / 128);  // (12, 32) = 384 CTAs
    qgemm1_kernel<<<grid, 256, SMEM1>>>(b_proj, theta);
    qgemm2_kernel<<<grid, 256, SMEM2>>>(b_comb, out);
}

// round 17
// speedup vs baseline: 1.1890x; 1.0121x over previous
#include <cuda_runtime.h>
#include <cuda_bf16.h>
#include <cuda_fp16.h>
#include <cstdint>
#include <math.h>

// M=4096, E=768. GEMM1 (x@Wp^T) bf16 3-term + fused quantum epilogue -> fp16 mid.
// GEMM2 (mid@Wc^T) single-product fp16 + bias.
// R16: R15 with the qgemm2 bBase OOB bug fixed (A_SM2 + bR*64).
#define MM 4096
#define NNE 768
#define KK 768

// ---- GEMM1: K=16 chunks, 32B rows ----
#define NCH1 48
#define A_SM1 4096            // 128 rows x 32B
#define B_SM1 2048            // 64 rows x 32B
#define BUF1 12288            // Ah, Al, Bh, Bl
// ---- GEMM2: K=32 chunks, 64B rows ----
#define NCH2 24
#define A_SM2 8192            // 128 x 64B
#define B_SM2 4096            // 64 x 64B
#define BUF2 12288
// ---- shared ----
#define NST 6
#define LOOKAHEAD 4
#define MB_OFF 73728
#define SMEM_BYTES 73856
#define EPI_STRIDE 68

// ---------------- device globals ----------------
__device__ __align__(16) __nv_bfloat16 g_xh[(size_t)MM * KK], g_xl[(size_t)MM * KK];
__device__ __align__(16) __nv_bfloat16 g_wph[(size_t)KK * NNE], g_wpl[(size_t)KK * NNE];
__device__ __align__(16) __half g_wc[(size_t)KK * NNE];
__device__ __align__(16) __half g_mid[(size_t)MM * NNE];

// ---------------- helpers ----------------
__device__ __forceinline__ uint32_t pk2(__nv_bfloat16 a, __nv_bfloat16 b) {
    __nv_bfloat162 v = __halves2bfloat162(a, b);
    return *(uint32_t*)&v;
}
__device__ __forceinline__ uint32_t pkh2(__half a, __half b) {
    __half2 v = __halves2half2(a, b);
    return *(uint32_t*)&v;
}
__device__ __forceinline__ void ldsm4(uint32_t& r0, uint32_t& r1, uint32_t& r2, uint32_t& r3,
                                      uint32_t addr) {
    asm volatile("ldmatrix.sync.aligned.m8n8.x4.shared.b16 {%0,%1,%2,%3}, [%4];"
                 : "=r"(r0), "=r"(r1), "=r"(r2), "=r"(r3) : "r"(addr));
}
__device__ __forceinline__ void mma_bf16(float* d, const uint32_t* a, const uint32_t* b) {
    asm volatile("mma.sync.aligned.m16n8k16.row.col.f32.bf16.bf16.f32 "
                 "{%0,%1,%2,%3}, {%4,%5,%6,%7}, {%8,%9}, {%0,%1,%2,%3};"
                 : "+f"(d[0]), "+f"(d[1]), "+f"(d[2]), "+f"(d[3])
                 : "r"(a[0]), "r"(a[1]), "r"(a[2]), "r"(a[3]), "r"(b[0]), "r"(b[1]));
}
__device__ __forceinline__ void mma_f16(float* d, const uint32_t* a, const uint32_t* b) {
    asm volatile("mma.sync.aligned.m16n8k16.row.col.f32.f16.f16.f32 "
                 "{%0,%1,%2,%3}, {%4,%5,%6,%7}, {%8,%9}, {%0,%1,%2,%3};"
                 : "+f"(d[0]), "+f"(d[1]), "+f"(d[2]), "+f"(d[3])
                 : "r"(a[0]), "r"(a[1]), "r"(a[2]), "r"(a[3]), "r"(b[0]), "r"(b[1]));
}
__device__ __forceinline__ void cpa16(uint32_t dst, const void* src) {
    asm volatile("cp.async.cg.shared.global [%0], [%1], 16;" :: "r"(dst), "l"(src));
}
__device__ __forceinline__ void mbar_init(uint32_t a, uint32_t n) {
    asm volatile("mbarrier.init.shared.b64 [%0], %1;" :: "r"(a), "r"(n) : "memory");
}
__device__ __forceinline__ void mbar_arrive(uint32_t a) {
    asm volatile("mbarrier.arrive.shared.b64 _, [%0];" :: "r"(a) : "memory");
}
__device__ __forceinline__ void mbar_wait(uint32_t a, uint32_t ph) {
    asm volatile("{\n\t.reg .pred P;\n\tWL_%=:\n\t"
                 "mbarrier.try_wait.parity.acquire.cta.shared::cta.b64 P, [%0], %1, 0x989680;\n\t"
                 "@!P bra WL_%=;\n\t}" :: "r"(a), "r"(ph) : "memory");
}
__device__ __forceinline__ void cpa_mbar(uint32_t a) {
    asm volatile("cp.async.mbarrier.arrive.noinc.shared::cta.b64 [%0];" :: "r"(a) : "memory");
}

// ---------------- fused prep: x split, Wp split, Wc -> fp16 ----------------
#define N4X (MM * KK / 4)
#define W4  (KK * NNE / 4)
__global__ void prep_kernel(const float* __restrict__ x, const float* __restrict__ wp,
                            const float* __restrict__ wc) {
    int i = blockIdx.x * blockDim.x + threadIdx.x;
    if (i < N4X + W4) {
        const float* src = (i < N4X) ? x : wp;
        int k = (i < N4X) ? i : i - N4X;
        __nv_bfloat16* hi = (i < N4X) ? g_xh : g_wph;
        __nv_bfloat16* lo = (i < N4X) ? g_xl : g_wpl;
        float4 v = ((const float4*)src)[k];
        float f[4] = {v.x, v.y, v.z, v.w};
        __nv_bfloat16 h[4], l[4];
#pragma unroll
        for (int j = 0; j < 4; j++) {
            h[j] = __float2bfloat16(f[j]);
            l[j] = __float2bfloat16(f[j] - __bfloat162float(h[j]));
        }
        *(uint2*)(hi + (size_t)k * 4) = make_uint2(pk2(h[0], h[1]), pk2(h[2], h[3]));
        *(uint2*)(lo + (size_t)k * 4) = make_uint2(pk2(l[0], l[1]), pk2(l[2], l[3]));
    } else if (i < N4X + 2 * W4) {
        int k = i - N4X - W4;
        float4 v = ((const float4*)wc)[k];
        *(uint2*)(g_wc + (size_t)k * 4) =
            make_uint2(pkh2(__float2half_rn(v.x), __float2half_rn(v.y)),
                       pkh2(__float2half_rn(v.z), __float2half_rn(v.w)));
    }
}

// ---------------- GEMM1: bf16 3-term, 6-stage rotating-issuer pipeline ----
__global__ __launch_bounds__(256, 3)
void qgemm1_kernel(const float* __restrict__ bias, const float* __restrict__ theta)
{
    extern __shared__ __align__(16) char smem[];
    const uint32_t sb = (uint32_t)__cvta_generic_to_shared(smem);
    const uint32_t mb = sb + MB_OFF;
    const int t = threadIdx.x, lane = t & 31, wid = t >> 5;
    const int warp_m = wid >> 1, warp_n = wid & 1;   // warp tile 32x32
    const int bm = blockIdx.y * 128, bn = blockIdx.x * 64;

    // ldsm addresses (32B rows, seg swizzle seg^((row>>2)&1))
    const int aRow = warp_m * 32 + (lane & 15);
    const uint32_t aBase = (uint32_t)(aRow * 32 + 16 * ((lane >> 4) ^ ((aRow >> 2) & 1)));
    const int bR = warp_n * 32 + (lane & 7) + ((lane >> 4) & 1) * 8;
    const uint32_t bBase = (uint32_t)(2 * A_SM1 + bR * 32 +
                                      16 * (((lane >> 3) & 1) ^ ((bR >> 2) & 1)));

    if (t == 0) {
#pragma unroll
        for (int s = 0; s < NST; s++) {
            mbar_init(mb + s * 8, 32);          // full: one warp's noinc arrivals
            mbar_init(mb + 48 + s * 8, 8);      // empty: 8 per-warp arrivals
        }
    }
    __syncthreads();

    // single-warp chunk issue: 24 cpa16 per lane = 12KB
    auto issue_chunk = [&](int j, int s) {
        const int ko = j * 16;
        const uint32_t d0 = sb + s * BUF1;
#pragma unroll
        for (int i = 0; i < 8; i++) {
            int idx = lane + 32 * i;
            int row = idx >> 1, seg = idx & 1;
            uint32_t dst = d0 + row * 32 + 16u * (seg ^ ((row >> 2) & 1));
            size_t off = (size_t)(bm + row) * KK + ko + seg * 8;
            cpa16(dst, g_xh + off);
            cpa16(dst + A_SM1, g_xl + off);
            if (i < 4) {   // B rows 0..63
                size_t boff = (size_t)(bn + row) * KK + ko + seg * 8;
                cpa16(dst + 2 * A_SM1, g_wph + boff);
                cpa16(dst + 2 * A_SM1 + B_SM1, g_wpl + boff);
            }
        }
        cpa_mbar(mb + s * 8);
    };

    // prologue: warps 0..3 fill stages 0..3
    if (wid < LOOKAHEAD) issue_chunk(wid, wid);

    float acc[2][4][4];
#pragma unroll
    for (int mt = 0; mt < 2; mt++)
#pragma unroll
        for (int nt = 0; nt < 4; nt++)
#pragma unroll
            for (int r = 0; r < 4; r++) acc[mt][nt][r] = 0.f;

    int s = 0, ph = 0;
    for (int c = 0; c < NCH1; ++c) {
        mbar_wait(mb + s * 8, ph);
        const uint32_t bufB = sb + s * BUF1;

        uint32_t bh[4][2], bl[4][2], af[2][4];
#pragma unroll
        for (int np = 0; np < 2; np++) {
            ldsm4(bh[2 * np][0], bh[2 * np][1], bh[2 * np + 1][0], bh[2 * np + 1][1],
                  bufB + bBase + np * 512);
            ldsm4(bl[2 * np][0], bl[2 * np][1], bl[2 * np + 1][0], bl[2 * np + 1][1],
                  bufB + bBase + B_SM1 + np * 512);
        }
#pragma unroll
        for (int mt = 0; mt < 2; mt++)
            ldsm4(af[mt][0], af[mt][1], af[mt][2], af[mt][3], bufB + aBase + mt * 512);
#pragma unroll
        for (int mt = 0; mt < 2; mt++)
#pragma unroll
            for (int nt = 0; nt < 4; nt++) mma_bf16(acc[mt][nt], af[mt], bh[nt]);
#pragma unroll
        for (int mt = 0; mt < 2; mt++)
#pragma unroll
            for (int nt = 0; nt < 4; nt++) mma_bf16(acc[mt][nt], af[mt], bl[nt]);
#pragma unroll
        for (int mt = 0; mt < 2; mt++)
            ldsm4(af[mt][0], af[mt][1], af[mt][2], af[mt][3],
                  bufB + A_SM1 + aBase + mt * 512);
#pragma unroll
        for (int mt = 0; mt < 2; mt++)
#pragma unroll
            for (int nt = 0; nt < 4; nt++) mma_bf16(acc[mt][nt], af[mt], bh[nt]);

        __syncwarp();
        if (lane == 0) mbar_arrive(mb + 48 + s * 8);
        if (wid == (c & 7)) {
            int j = c + LOOKAHEAD;
            if (j < NCH1) {
                int k = j / 6, sj = j - k * 6;
                if (k > 0) mbar_wait(mb + 48 + sj * 8, (k + 1) & 1);
                issue_chunk(j, sj);
            }
        }
        if (++s == NST) { s = 0; ph ^= 1; }
    }
    __syncthreads();

    float* smf = (float*)smem;
#pragma unroll
    for (int mt = 0; mt < 2; mt++)
#pragma unroll
        for (int nt = 0; nt < 4; nt++) {
            int r0 = warp_m * 32 + mt * 16 + (lane >> 2);
            int col = warp_n * 32 + nt * 8 + (lane & 3) * 2;
            smf[r0 * EPI_STRIDE + col]           = acc[mt][nt][0];
            smf[r0 * EPI_STRIDE + col + 1]       = acc[mt][nt][1];
            smf[(r0 + 8) * EPI_STRIDE + col]     = acc[mt][nt][2];
            smf[(r0 + 8) * EPI_STRIDE + col + 1] = acc[mt][nt][3];
        }
    __syncthreads();

    float th[8];
#pragma unroll
    for (int j = 0; j < 8; j++) th[j] = theta[j];
#pragma unroll
    for (int i = 0; i < 4; i++) {
        int gid = t + i * 256;
        int row = gid >> 3, head = gid & 7;
        const float* src = smf + row * EPI_STRIDE + head * 8;
        float cc[8];
#pragma unroll
        for (int j = 0; j < 8; j++)
            cc[j] = cosf(src[j] + bias[bn + head * 8 + j] + th[j]);
        float o[8];
        float p = cc[0];
#pragma unroll
        for (int w = 1; w < 8; w++) { p *= cc[w]; o[w] = p; }
        float q = cc[1];
#pragma unroll
        for (int w = 2; w < 8; w++) q *= cc[w];
        o[0] = q;
        __half h[8];
#pragma unroll
        for (int j = 0; j < 8; j++) h[j] = __float2half_rn(o[j]);
        size_t doff = (size_t)(bm + row) * NNE + bn + head * 8;
        *(uint4*)(g_mid + doff) = make_uint4(pkh2(h[0], h[1]), pkh2(h[2], h[3]),
                                             pkh2(h[4], h[5]), pkh2(h[6], h[7]));
    }
}

// ---------------- GEMM2: fp16 single product, 6-stage rotating issuer ----
__global__ __launch_bounds__(256, 3)
void qgemm2_kernel(const float* __restrict__ bias, float* __restrict__ out)
{
    extern __shared__ __align__(16) char smem[];
    const uint32_t sb = (uint32_t)__cvta_generic_to_shared(smem);
    const uint32_t mb = sb + MB_OFF;
    const int t = threadIdx.x, lane = t & 31, wid = t >> 5;
    const int warp_m = wid >> 1, warp_n = wid & 1;
    const int bm = blockIdx.y * 128, bn = blockIdx.x * 64;

    // ldsm addresses (64B rows, seg swizzle seg^((row>>1)&3))
    const int aRow = warp_m * 32 + (lane & 15);
    const int aSw = (aRow >> 1) & 3;
    const uint32_t aBase = (uint32_t)(aRow * 64);
    const uint32_t aK0 = 16u * (((lane >> 4)) ^ aSw);
    const uint32_t aK1 = 16u * ((2 + (lane >> 4)) ^ aSw);
    const int bR = warp_n * 32 + (lane & 7) + ((lane >> 4) & 1) * 8;
    const int bSw = (bR >> 1) & 3;
    const uint32_t bBase = (uint32_t)(A_SM2 + bR * 64);   // FIXED (was 2*A_SM2)
    const uint32_t bK0 = 16u * (((lane >> 3) & 1) ^ bSw);
    const uint32_t bK1 = 16u * ((2 + ((lane >> 3) & 1)) ^ bSw);

    if (t == 0) {
#pragma unroll
        for (int s = 0; s < NST; s++) {
            mbar_init(mb + s * 8, 32);
            mbar_init(mb + 48 + s * 8, 8);
        }
    }
    __syncthreads();

    auto issue_chunk = [&](int j, int s) {
        const int ko = j * 32;
        const uint32_t d0 = sb + s * BUF2;
#pragma unroll
        for (int i = 0; i < 16; i++) {
            int idx = lane + 32 * i;
            int row = idx >> 2, seg = idx & 3;
            uint32_t dst = d0 + row * 64 + 16u * (seg ^ ((row >> 1) & 3));
            cpa16(dst, g_mid + (size_t)(bm + row) * KK + ko + seg * 8);
            if (i < 8) {   // B rows 0..63
                cpa16(dst + A_SM2, g_wc + (size_t)(bn + row) * KK + ko + seg * 8);
            }
        }
        cpa_mbar(mb + s * 8);
    };

    if (wid < LOOKAHEAD) issue_chunk(wid, wid);

    float acc[2][4][4];
#pragma unroll
    for (int mt = 0; mt < 2; mt++)
#pragma unroll
        for (int nt = 0; nt < 4; nt++)
#pragma unroll
            for (int r = 0; r < 4; r++) acc[mt][nt][r] = 0.f;

    int s = 0, ph = 0;
    for (int c = 0; c < NCH2; ++c) {
        mbar_wait(mb + s * 8, ph);
        const uint32_t bufB = sb + s * BUF2;
#pragma unroll
        for (int ks = 0; ks < 2; ks++) {
            const uint32_t aKo = ks ? aK1 : aK0;
            const uint32_t bKo = ks ? bK1 : bK0;
            uint32_t bh[4][2], af[2][4];
#pragma unroll
            for (int np = 0; np < 2; np++)
                ldsm4(bh[2 * np][0], bh[2 * np][1], bh[2 * np + 1][0], bh[2 * np + 1][1],
                      bufB + bBase + np * 1024 + bKo);
#pragma unroll
            for (int mt = 0; mt < 2; mt++)
                ldsm4(af[mt][0], af[mt][1], af[mt][2], af[mt][3],
                      bufB + aBase + mt * 1024 + aKo);
#pragma unroll
            for (int mt = 0; mt < 2; mt++)
#pragma unroll
                for (int nt = 0; nt < 4; nt++) mma_f16(acc[mt][nt], af[mt], bh[nt]);
        }

        __syncwarp();
        if (lane == 0) mbar_arrive(mb + 48 + s * 8);
        if (wid == (c & 7)) {
            int j = c + LOOKAHEAD;
            if (j < NCH2) {
                int k = j / 6, sj = j - k * 6;
                if (k > 0) mbar_wait(mb + 48 + sj * 8, (k + 1) & 1);
                issue_chunk(j, sj);
            }
        }
        if (++s == NST) { s = 0; ph ^= 1; }
    }
    __syncthreads();

    float* smf = (float*)smem;
#pragma unroll
    for (int mt = 0; mt < 2; mt++)
#pragma unroll
        for (int nt = 0; nt < 4; nt++) {
            int r0 = warp_m * 32 + mt * 16 + (lane >> 2);
            int col = warp_n * 32 + nt * 8 + (lane & 3) * 2;
            smf[r0 * EPI_STRIDE + col]           = acc[mt][nt][0];
            smf[r0 * EPI_STRIDE + col + 1]       = acc[mt][nt][1];
            smf[(r0 + 8) * EPI_STRIDE + col]     = acc[mt][nt][2];
            smf[(r0 + 8) * EPI_STRIDE + col + 1] = acc[mt][nt][3];
        }
    __syncthreads();

#pragma unroll
    for (int i = 0; i < 8; i++) {
        int idx = t + i * 256;
        int row = idx >> 4, c4 = idx & 15;
        const float* src = smf + row * EPI_STRIDE + c4 * 4;
        float4 v;
        v.x = src[0] + bias[bn + c4 * 4 + 0];
        v.y = src[1] + bias[bn + c4 * 4 + 1];
        v.z = src[2] + bias[bn + c4 * 4 + 2];
        v.w = src[3] + bias[bn + c4 * 4 + 3];
        *(float4*)(out + (size_t)(bm + row) * NNE + bn + c4 * 4) = v;
    }
}

// ---------------- launch ----------------
extern "C" void kernel_launch(void* const* d_in, const int* in_sizes, int n_in,
                              void* d_out, int out_size)
{
    const float* x      = (const float*)d_in[0];
    const float* W_proj = (const float*)d_in[1];
    const float* b_proj = (const float*)d_in[2];
    const float* theta  = (const float*)d_in[3];
    const float* W_comb = (const float*)d_in[4];
    const float* b_comb = (const float*)d_in[5];
    float* out = (float*)d_out;

    cudaFuncSetAttribute(qgemm1_kernel, cudaFuncAttributeMaxDynamicSharedMemorySize, SMEM_BYTES);
    cudaFuncSetAttribute(qgemm2_kernel, cudaFuncAttributeMaxDynamicSharedMemorySize, SMEM_BYTES);

    int total4 = N4X + 2 * W4;
    prep_kernel<<<(total4 + 255) / 256, 256>>>(x, W_proj, W_comb);

    dim3 grid(NNE / 64, MM / 128);  // (12, 32) = 384 CTAs
    qgemm1_kernel<<<grid, 256, SMEM_BYTES>>>(b_proj, theta);
    qgemm2_kernel<<<grid, 256, SMEM_BYTES>>>(b_comb, out);
}